// round 6
// baseline (speedup 1.0000x reference)
#include <cuda_runtime.h>
#include <math.h>

// Problem constants
#define BATCH 2
#define T 2048
#define D 1024
#define H 16
#define HD 64
#define MROWS (BATCH * T)      // 4096
#define THRESH 0.29514f
#define SHARP 15.0f
#define LN_EPS 1e-5f
#define NORM_EPS 1e-12f

// ---------------------------------------------------------------------------
// Scratch (no allocations allowed -> __device__ globals)
// ---------------------------------------------------------------------------
__device__ float g_xn[MROWS * D];     // layernorm output, row-major [4096,1024]
__device__ float g_qraw[MROWS * D];   // x_norm @ Wq, row-major
__device__ float g_kraw[MROWS * D];   // x_norm @ Wk
__device__ float g_vraw[MROWS * D];   // x @ Wv
__device__ float g_qh[MROWS * D];     // head-major [b,h,t,d], l2-normalized
__device__ float g_kh[MROWS * D];
__device__ float g_vh[MROWS * D];
__device__ float g_gq[BATCH * H * T]; // gate_q[b,h,t]
__device__ float g_gk[BATCH * H * T]; // gate_k[b,h,s]
__device__ float g_coll[MROWS * D];   // collapse, row-major [b,t,D]

// ---------------------------------------------------------------------------
// 1) LayerNorm: one block per row of 1024
// ---------------------------------------------------------------------------
__global__ __launch_bounds__(256) void ln_kernel(
    const float* __restrict__ x, const float* __restrict__ w,
    const float* __restrict__ b, float* __restrict__ out)
{
    int row = blockIdx.x;
    const float* xr = x + (size_t)row * D;
    float s = 0.f, ss = 0.f;
    float loc[4];
#pragma unroll
    for (int it = 0; it < 4; it++) {
        float v = xr[threadIdx.x + it * 256];
        loc[it] = v;
        s += v; ss += v * v;
    }
#pragma unroll
    for (int o = 16; o > 0; o >>= 1) {
        s  += __shfl_xor_sync(0xFFFFFFFFu, s,  o);
        ss += __shfl_xor_sync(0xFFFFFFFFu, ss, o);
    }
    __shared__ float red[16];
    __shared__ float mu_s, rstd_s;
    int warp = threadIdx.x >> 5, lane = threadIdx.x & 31;
    if (lane == 0) { red[warp] = s; red[warp + 8] = ss; }
    __syncthreads();
    if (threadIdx.x == 0) {
        float S = 0.f, SS = 0.f;
        for (int i = 0; i < 8; i++) { S += red[i]; SS += red[i + 8]; }
        float mu = S / D;
        float var = SS / D - mu * mu;
        mu_s = mu;
        rstd_s = rsqrtf(var + LN_EPS);
    }
    __syncthreads();
    float mu = mu_s, rstd = rstd_s;
    float* orow = out + (size_t)row * D;
#pragma unroll
    for (int it = 0; it < 4; it++) {
        int c = threadIdx.x + it * 256;
        orow[c] = (loc[it] - mu) * rstd * w[c] + b[c];
    }
}

// ---------------------------------------------------------------------------
// 2) SGEMM: C[M,N] = A[M,K] * B[K,N] (+bias). 128x128 tile, BK=8.
//    Microtile 8x(4+4) split-N: thread covers cols tn*4..+3 and 64+tn*4..+3
//    -> both B fragment LDS.128 are conflict-free (16B lane stride).
//    Global->register prefetch hides tile-boundary LDG latency.
// ---------------------------------------------------------------------------
template <bool BIAS>
__global__ __launch_bounds__(256) void sgemm_kernel(
    const float* __restrict__ A, const float* __restrict__ Bm,
    const float* __restrict__ bias, float* __restrict__ C,
    int M, int N, int K)
{
    __shared__ float As[8][128];
    __shared__ float Bs[8][132];  // slight pad

    int tid = threadIdx.x;
    int tn = tid & 15;       // 0..15 -> N micro (split: tn*4 and 64+tn*4)
    int tm = tid >> 4;       // 0..15 -> M micro
    int bx = blockIdx.x;     // N tile
    int by = blockIdx.y;     // M tile

    int arow = (by << 7) + (tid >> 1);
    int acol = (tid & 1) << 2;
    int brow = tid >> 5;
    int bcolL = (tid & 31) << 2;
    int bcol = (bx << 7) + bcolL;

    const float* Ap = A + (size_t)arow * K + acol;
    const float* Bp = Bm + (size_t)brow * N + bcol;

    float acc[8][8];
#pragma unroll
    for (int i = 0; i < 8; i++)
#pragma unroll
        for (int j = 0; j < 8; j++) acc[i][j] = 0.f;

    // prefetch first tile
    float4 av = *(const float4*)(Ap);
    float4 bv = *(const float4*)(Bp);

    for (int k0 = 0; k0 < K; k0 += 8) {
        int ar = tid >> 1;
        As[acol + 0][ar] = av.x;
        As[acol + 1][ar] = av.y;
        As[acol + 2][ar] = av.z;
        As[acol + 3][ar] = av.w;
        *(float4*)&Bs[brow][bcolL] = bv;
        __syncthreads();

        // prefetch next tile while computing this one
        if (k0 + 8 < K) {
            av = *(const float4*)(Ap + k0 + 8);
            bv = *(const float4*)(Bp + (size_t)(k0 + 8) * N);
        }

#pragma unroll
        for (int kk = 0; kk < 8; kk++) {
            float a[8], b[8];
            *(float4*)(a)     = *(float4*)&As[kk][tm * 8];
            *(float4*)(a + 4) = *(float4*)&As[kk][tm * 8 + 4];
            *(float4*)(b)     = *(float4*)&Bs[kk][tn * 4];        // cols tn*4..+3
            *(float4*)(b + 4) = *(float4*)&Bs[kk][64 + tn * 4];   // cols 64+tn*4..+3
#pragma unroll
            for (int i = 0; i < 8; i++)
#pragma unroll
                for (int j = 0; j < 8; j++)
                    acc[i][j] += a[i] * b[j];
        }
        __syncthreads();
    }

    int crow0 = (by << 7) + tm * 8;
    int c0 = (bx << 7) + tn * 4;        // first 4 cols
    int c1 = c0 + 64;                   // second 4 cols
    float4 bias0, bias1;
    if (BIAS) {
        bias0 = *(const float4*)(bias + c0);
        bias1 = *(const float4*)(bias + c1);
    }
#pragma unroll
    for (int i = 0; i < 8; i++) {
        float* cr = C + (size_t)(crow0 + i) * N;
        float4 v0 = make_float4(acc[i][0], acc[i][1], acc[i][2], acc[i][3]);
        float4 v1 = make_float4(acc[i][4], acc[i][5], acc[i][6], acc[i][7]);
        if (BIAS) {
            v0.x += bias0.x; v0.y += bias0.y; v0.z += bias0.z; v0.w += bias0.w;
            v1.x += bias1.x; v1.y += bias1.y; v1.z += bias1.z; v1.w += bias1.w;
        }
        *(float4*)(cr + c0) = v0;
        *(float4*)(cr + c1) = v1;
    }
}

// ---------------------------------------------------------------------------
// 3) Pack to head-major [b,h,t,d]; optional l2-norm + gate dot.
//    One warp per (row, head). 8 warps/block.
// ---------------------------------------------------------------------------
__global__ __launch_bounds__(256) void pack_norm_kernel(
    const float* __restrict__ raw, const float* __restrict__ gvec,
    float* __restrict__ dst, float* __restrict__ gate, int donorm)
{
    int w = blockIdx.x * 8 + (threadIdx.x >> 5);
    int lane = threadIdx.x & 31;
    int row = w >> 4;      // 0..4095
    int h = w & 15;
    int b = row >> 11;     // /T (T=2048)
    int t = row & 2047;

    const float* src = raw + (size_t)row * D + h * HD;
    float2 v = *(const float2*)(src + lane * 2);

    float scale = 1.f;
    if (donorm) {
        float ss = v.x * v.x + v.y * v.y;
#pragma unroll
        for (int o = 16; o > 0; o >>= 1)
            ss += __shfl_xor_sync(0xFFFFFFFFu, ss, o);
        float n = sqrtf(ss);
        scale = 1.f / fmaxf(n, NORM_EPS);
    }
    float2 o2;
    o2.x = v.x * scale;
    o2.y = v.y * scale;

    int bh = b * H + h;
    float* d = dst + ((size_t)bh * T + t) * HD + lane * 2;
    *(float2*)d = o2;

    if (gvec != nullptr) {
        float g = o2.x * gvec[lane * 2] + o2.y * gvec[lane * 2 + 1];
#pragma unroll
        for (int o = 16; o > 0; o >>= 1)
            g += __shfl_xor_sync(0xFFFFFFFFu, g, o);
        if (lane == 0) gate[(size_t)bh * T + t] = g;
    }
}

// ---------------------------------------------------------------------------
// 4) Attention (flash-style): block = (q-tile of 64 rows, one (b,h)).
//    Loops over s-tiles of 32: S = Q K^T, m = sigmoid((S-th)*sh)*gq*gk,
//    O += m V. Never materializes the 2048x2048 align matrix.
//    K transposed in smem (conflict-free QK); PV loop fully vectorized
//    (LDS.128 for both Ss and Vs).
// ---------------------------------------------------------------------------
__global__ __launch_bounds__(256) void attn_kernel(
    const float* __restrict__ qh, const float* __restrict__ kh,
    const float* __restrict__ vh, const float* __restrict__ gq,
    const float* __restrict__ gk, float* __restrict__ coll)
{
    __shared__ float Qs[64][68];
    __shared__ float Kt[64][34];   // transposed K tile: Kt[d][s], even stride
    __shared__ float Vs[32][68];
    __shared__ float Ss[64][36];
    __shared__ float gqs[64];
    __shared__ float gks[32];

    int bh = blockIdx.y;
    int t0 = blockIdx.x * 64;
    int tid = threadIdx.x;
    int tx = tid & 15;     // 16
    int ty = tid >> 4;     // 16

    const float* Qb = qh + ((size_t)bh * T + t0) * HD;
    // load Q tile (64x64): 1024 float4 / 256 threads = 4 each
#pragma unroll
    for (int it = 0; it < 4; it++) {
        int i = tid + it * 256;
        int r = i >> 4, c = (i & 15) << 2;
        float4 v = *(const float4*)(Qb + r * HD + c);
        Qs[r][c] = v.x; Qs[r][c + 1] = v.y; Qs[r][c + 2] = v.z; Qs[r][c + 3] = v.w;
    }
    if (tid < 64) gqs[tid] = gq[(size_t)bh * T + t0 + tid];

    float o[4][4];
#pragma unroll
    for (int i = 0; i < 4; i++)
#pragma unroll
        for (int j = 0; j < 4; j++) o[i][j] = 0.f;

    // per-thread fixed (s-row, d-col) for the K/V cooperative load
    int lr0 = tid >> 4;            // rows 0..15  (it=0)
    int lr1 = (tid + 256) >> 4;    // rows 16..31 (it=1)
    int lc = (tid & 15) << 2;

    for (int s0 = 0; s0 < T; s0 += 32) {
        const float* Kb = kh + ((size_t)bh * T + s0) * HD;
        const float* Vb = vh + ((size_t)bh * T + s0) * HD;
        // prefetch into registers (no smem touched yet)
        float4 kv0 = *(const float4*)(Kb + lr0 * HD + lc);
        float4 vv0 = *(const float4*)(Vb + lr0 * HD + lc);
        float4 kv1 = *(const float4*)(Kb + lr1 * HD + lc);
        float4 vv1 = *(const float4*)(Vb + lr1 * HD + lc);
        float gkr = (tid < 32) ? gk[(size_t)bh * T + s0 + tid] : 0.f;

        __syncthreads();   // previous-iteration readers of Kt/Vs/Ss done
        // K transposed scatter: Kt[d][s] = K[s][d]
        Kt[lc + 0][lr0] = kv0.x; Kt[lc + 1][lr0] = kv0.y;
        Kt[lc + 2][lr0] = kv0.z; Kt[lc + 3][lr0] = kv0.w;
        Kt[lc + 0][lr1] = kv1.x; Kt[lc + 1][lr1] = kv1.y;
        Kt[lc + 2][lr1] = kv1.z; Kt[lc + 3][lr1] = kv1.w;
        Vs[lr0][lc] = vv0.x; Vs[lr0][lc + 1] = vv0.y; Vs[lr0][lc + 2] = vv0.z; Vs[lr0][lc + 3] = vv0.w;
        Vs[lr1][lc] = vv1.x; Vs[lr1][lc + 1] = vv1.y; Vs[lr1][lc + 2] = vv1.z; Vs[lr1][lc + 3] = vv1.w;
        if (tid < 32) gks[tid] = gkr;
        __syncthreads();

        // S = Q K^T : thread computes 4 rows x 2 cols.
        // Q via LDS.128 (per 4 d's), K via conflict-free LDS.64.
        float acc[4][2];
#pragma unroll
        for (int i = 0; i < 4; i++) { acc[i][0] = 0.f; acc[i][1] = 0.f; }
#pragma unroll
        for (int d4 = 0; d4 < 64; d4 += 4) {
            float4 q0 = *(const float4*)&Qs[ty * 4 + 0][d4];
            float4 q1 = *(const float4*)&Qs[ty * 4 + 1][d4];
            float4 q2 = *(const float4*)&Qs[ty * 4 + 2][d4];
            float4 q3 = *(const float4*)&Qs[ty * 4 + 3][d4];
#pragma unroll
            for (int k = 0; k < 4; k++) {
                float2 kv = *(const float2*)&Kt[d4 + k][tx * 2];
                float qa = (k == 0) ? q0.x : (k == 1) ? q0.y : (k == 2) ? q0.z : q0.w;
                float qb = (k == 0) ? q1.x : (k == 1) ? q1.y : (k == 2) ? q1.z : q1.w;
                float qc = (k == 0) ? q2.x : (k == 1) ? q2.y : (k == 2) ? q2.z : q2.w;
                float qd = (k == 0) ? q3.x : (k == 1) ? q3.y : (k == 2) ? q3.z : q3.w;
                acc[0][0] += qa * kv.x; acc[0][1] += qa * kv.y;
                acc[1][0] += qb * kv.x; acc[1][1] += qb * kv.y;
                acc[2][0] += qc * kv.x; acc[2][1] += qc * kv.y;
                acc[3][0] += qd * kv.x; acc[3][1] += qd * kv.y;
            }
        }
        // modulation = sigmoid((align - th)*sh) * gq[t] * gk[s]
#pragma unroll
        for (int i = 0; i < 4; i++) {
            float gqi = gqs[ty * 4 + i];
#pragma unroll
            for (int j = 0; j < 2; j++) {
                float z = (acc[i][j] - THRESH) * SHARP;
                float m = 1.f / (1.f + __expf(-z));
                Ss[ty * 4 + i][tx * 2 + j] = m * gqi * gks[tx * 2 + j];
            }
        }
        __syncthreads();

        // O += Ss * Vs : s unrolled by 4, all smem reads LDS.128
#pragma unroll
        for (int s = 0; s < 32; s += 4) {
            float4 a0 = *(const float4*)&Ss[ty * 4 + 0][s];
            float4 a1 = *(const float4*)&Ss[ty * 4 + 1][s];
            float4 a2 = *(const float4*)&Ss[ty * 4 + 2][s];
            float4 a3 = *(const float4*)&Ss[ty * 4 + 3][s];
#pragma unroll
            for (int k = 0; k < 4; k++) {
                float4 bv = *(const float4*)&Vs[s + k][tx * 4];
                float sa = (k == 0) ? a0.x : (k == 1) ? a0.y : (k == 2) ? a0.z : a0.w;
                float sb = (k == 0) ? a1.x : (k == 1) ? a1.y : (k == 2) ? a1.z : a1.w;
                float sc = (k == 0) ? a2.x : (k == 1) ? a2.y : (k == 2) ? a2.z : a2.w;
                float sd = (k == 0) ? a3.x : (k == 1) ? a3.y : (k == 2) ? a3.z : a3.w;
                o[0][0] += sa * bv.x; o[0][1] += sa * bv.y; o[0][2] += sa * bv.z; o[0][3] += sa * bv.w;
                o[1][0] += sb * bv.x; o[1][1] += sb * bv.y; o[1][2] += sb * bv.z; o[1][3] += sb * bv.w;
                o[2][0] += sc * bv.x; o[2][1] += sc * bv.y; o[2][2] += sc * bv.z; o[2][3] += sc * bv.w;
                o[3][0] += sd * bv.x; o[3][1] += sd * bv.y; o[3][2] += sd * bv.z; o[3][3] += sd * bv.w;
            }
        }
    }

    // write collapse back in row-major [b,t,D] with head offset
    int b = bh >> 4, h = bh & 15;
#pragma unroll
    for (int i = 0; i < 4; i++) {
        int gt = t0 + ty * 4 + i;
        float* dst = coll + ((size_t)(b * T + gt)) * D + h * HD + tx * 4;
        float4 v = make_float4(o[i][0], o[i][1], o[i][2], o[i][3]);
        *(float4*)dst = v;
    }
}

// ---------------------------------------------------------------------------
// Launch
// ---------------------------------------------------------------------------
extern "C" void kernel_launch(void* const* d_in, const int* in_sizes, int n_in,
                              void* d_out, int out_size)
{
    const float* x    = (const float*)d_in[0];
    const float* Wq   = (const float*)d_in[1];
    const float* Wk   = (const float*)d_in[2];
    const float* Wv   = (const float*)d_in[3];
    const float* gq   = (const float*)d_in[4];
    const float* gk   = (const float*)d_in[5];
    const float* Wo   = (const float*)d_in[6];
    const float* bo   = (const float*)d_in[7];
    const float* ln_w = (const float*)d_in[8];
    const float* ln_b = (const float*)d_in[9];
    float* out = (float*)d_out;

    float *xn, *qraw, *kraw, *vraw, *qh, *kh, *vh, *gqv, *gkv, *coll;
    cudaGetSymbolAddress((void**)&xn,   g_xn);
    cudaGetSymbolAddress((void**)&qraw, g_qraw);
    cudaGetSymbolAddress((void**)&kraw, g_kraw);
    cudaGetSymbolAddress((void**)&vraw, g_vraw);
    cudaGetSymbolAddress((void**)&qh,   g_qh);
    cudaGetSymbolAddress((void**)&kh,   g_kh);
    cudaGetSymbolAddress((void**)&vh,   g_vh);
    cudaGetSymbolAddress((void**)&gqv,  g_gq);
    cudaGetSymbolAddress((void**)&gkv,  g_gk);
    cudaGetSymbolAddress((void**)&coll, g_coll);

    // 1) LayerNorm
    ln_kernel<<<MROWS, 256>>>(x, ln_w, ln_b, xn);

    // 2) Q/K/V projections
    dim3 ggrid(D / 128, MROWS / 128);
    sgemm_kernel<false><<<ggrid, 256>>>(xn, Wq, nullptr, qraw, MROWS, D, D);
    sgemm_kernel<false><<<ggrid, 256>>>(xn, Wk, nullptr, kraw, MROWS, D, D);
    sgemm_kernel<false><<<ggrid, 256>>>(x,  Wv, nullptr, vraw, MROWS, D, D);

    // 3) l2-normalize + gates + head-major pack
    int pack_blocks = (MROWS * H) / 8;   // 8 warps/block
    pack_norm_kernel<<<pack_blocks, 256>>>(qraw, gq, qh, gqv, 1);
    pack_norm_kernel<<<pack_blocks, 256>>>(kraw, gk, kh, gkv, 1);
    pack_norm_kernel<<<pack_blocks, 256>>>(vraw, nullptr, vh, nullptr, 0);

    // 4) fused gated attention
    dim3 agrid(T / 64, BATCH * H);
    attn_kernel<<<agrid, 256>>>(qh, kh, vh, gqv, gkv, coll);

    // 5) output projection + bias
    sgemm_kernel<true><<<ggrid, 256>>>(coll, Wo, bo, out, MROWS, D, D);
}